// round 1
// baseline (speedup 1.0000x reference)
#include <cuda_runtime.h>
#include <math.h>

#define GG   64
#define NN   1024
#define DIN  128
#define DH   256
#define DOUT 10
#define MT   (GG * NN)   // 65536 nodes total

// ---- scratch (no allocations allowed) ----
__device__ float g_invn[MT];          // 1/||x_m|| (with eps)
__device__ float g_selfw[MT];         // ||xn_m||^2 = sumsq/(sumsq+eps)
__device__ float g_s[GG * DIN];       // per-graph sum of normalized rows
__device__ float g_w[MT];             // per-node adjacency column-sum weight
__device__ float g_upart[GG * 8 * DH];// per-(graph,rowtile) partial of u = sum_m w_m h_m

// ============================================================
// Kernel 1: per-graph row norms + s_g = sum of normalized rows
// grid = G blocks, 512 threads (16 warps, 64 nodes per warp)
// ============================================================
__global__ void k_norms(const float* __restrict__ x) {
    const int g    = blockIdx.x;
    const int tid  = threadIdx.x;
    const int w    = tid >> 5;
    const int lane = tid & 31;

    __shared__ float spart[16][DIN];   // deterministic per-warp partials

    float s0 = 0.f, s1 = 0.f, s2 = 0.f, s3 = 0.f;

    for (int n = w; n < NN; n += 16) {
        const int node = g * NN + n;
        const float4 v = *(const float4*)(x + (size_t)node * DIN + lane * 4);
        float sq = v.x * v.x + v.y * v.y + v.z * v.z + v.w * v.w;
        #pragma unroll
        for (int o = 16; o > 0; o >>= 1) sq += __shfl_xor_sync(0xffffffffu, sq, o);
        const float invn = rsqrtf(sq + 1e-24f);
        if (lane == 0) {
            g_invn[node]  = invn;
            g_selfw[node] = sq * invn * invn;   // exact ||xn||^2 incl. eps
        }
        s0 += invn * v.x; s1 += invn * v.y; s2 += invn * v.z; s3 += invn * v.w;
    }
    spart[w][lane * 4 + 0] = s0;
    spart[w][lane * 4 + 1] = s1;
    spart[w][lane * 4 + 2] = s2;
    spart[w][lane * 4 + 3] = s3;
    __syncthreads();
    if (tid < DIN) {
        float s = 0.f;
        #pragma unroll
        for (int i = 0; i < 16; i++) s += spart[i][tid];
        g_s[g * DIN + tid] = s;
    }
}

// ============================================================
// Kernel 2: per-node weight  w_m = invn_m * (s_g . x_m) - ||xn_m||^2
// one warp per node; grid = MT/8 blocks of 256 threads
// ============================================================
__global__ void k_wvec(const float* __restrict__ x) {
    const int node = blockIdx.x * 8 + (threadIdx.x >> 5);
    const int lane = threadIdx.x & 31;
    const int g    = node >> 10;

    const float4 v  = *(const float4*)(x   + (size_t)node * DIN + lane * 4);
    const float4 sv = *(const float4*)(g_s + g * DIN + lane * 4);
    float d = v.x * sv.x + v.y * sv.y + v.z * sv.z + v.w * sv.w;
    #pragma unroll
    for (int o = 16; o > 0; o >>= 1) d += __shfl_xor_sync(0xffffffffu, d, o);
    if (lane == 0) g_w[node] = g_invn[node] * d - g_selfw[node];
}

// ============================================================
// Kernel 3: fused SGEMM  h = relu(X @ W1 + b1)  with epilogue
//           u_partial[col] += sum_rows w_m * h[m,col]
// 128x128 output tile, 8x8 per thread, BK=8, 256 threads.
// grid = (DH/128, MT/128)
// ============================================================
__global__ __launch_bounds__(256, 2)
void k_main(const float* __restrict__ x,
            const float* __restrict__ W1,
            const float* __restrict__ b1) {
    const int cb  = blockIdx.x;         // 0..1 (column tile)
    const int rb  = blockIdx.y;         // 0..511 (row tile)
    const int m0  = rb * 128;
    const int n0  = cb * 128;
    const int tid = threadIdx.x;
    const int tx  = tid & 15;
    const int ty  = tid >> 4;

    __shared__ float As[8][128];
    __shared__ float Bs[8][128];
    __shared__ float Red[16][128];

    float acc[8][8];
    #pragma unroll
    for (int i = 0; i < 8; i++)
        #pragma unroll
        for (int j = 0; j < 8; j++) acc[i][j] = 0.f;

    const int arow = tid >> 1;           // 0..127
    const int akk  = (tid & 1) * 4;      // 0 or 4
    const int bkk  = tid >> 5;           // 0..7
    const int bcol = (tid & 31) * 4;

    const float* xg = x  + (size_t)(m0 + arow) * DIN + akk;
    const float* wg = W1 + (size_t)bkk * DH + n0 + bcol;

    for (int kc = 0; kc < DIN; kc += 8) {
        const float4 av = *(const float4*)(xg + kc);
        const float4 bv = *(const float4*)(wg + (size_t)kc * DH);
        __syncthreads();   // previous chunk's reads complete
        As[akk + 0][arow] = av.x;
        As[akk + 1][arow] = av.y;
        As[akk + 2][arow] = av.z;
        As[akk + 3][arow] = av.w;
        *(float4*)&Bs[bkk][bcol] = bv;
        __syncthreads();
        #pragma unroll
        for (int kk = 0; kk < 8; kk++) {
            float a[8], b[8];
            *(float4*)(a)     = *(const float4*)&As[kk][ty * 8];
            *(float4*)(a + 4) = *(const float4*)&As[kk][ty * 8 + 4];
            *(float4*)(b)     = *(const float4*)&Bs[kk][tx * 8];
            *(float4*)(b + 4) = *(const float4*)&Bs[kk][tx * 8 + 4];
            #pragma unroll
            for (int i = 0; i < 8; i++)
                #pragma unroll
                for (int j = 0; j < 8; j++)
                    acc[i][j] = fmaf(a[i], b[j], acc[i][j]);
        }
    }

    // epilogue: +b1, relu, * w_m, reduce rows
    float bv1[8];
    #pragma unroll
    for (int j = 0; j < 8; j++) bv1[j] = b1[n0 + tx * 8 + j];

    float p[8];
    #pragma unroll
    for (int j = 0; j < 8; j++) p[j] = 0.f;

    #pragma unroll
    for (int i = 0; i < 8; i++) {
        const float wv = g_w[m0 + ty * 8 + i];
        #pragma unroll
        for (int j = 0; j < 8; j++) {
            float h = acc[i][j] + bv1[j];
            h = h > 0.f ? h : 0.f;
            p[j] = fmaf(wv, h, p[j]);
        }
    }

    __syncthreads();
    #pragma unroll
    for (int j = 0; j < 8; j++) Red[ty][tx * 8 + j] = p[j];
    __syncthreads();

    if (tid < 128) {
        float s = 0.f;
        #pragma unroll
        for (int t = 0; t < 16; t++) s += Red[t][tid];
        const int g = rb >> 3;       // graph id (8 row tiles per graph)
        const int r = rb & 7;        // row tile within graph
        g_upart[(g * 8 + r) * DH + n0 + tid] = s;
    }
}

// ============================================================
// Kernel 4: reduce partials, (u/N) @ W2 + b2, log-softmax
// grid = G blocks, 256 threads (thread j owns hidden channel j)
// ============================================================
__global__ void k_final(const float* __restrict__ W2,
                        const float* __restrict__ b2,
                        float* __restrict__ out) {
    const int g = blockIdx.x;
    const int j = threadIdx.x;   // 0..255

    float u = 0.f;
    #pragma unroll
    for (int r = 0; r < 8; r++) u += g_upart[(g * 8 + r) * DH + j];
    u *= (1.0f / NN);

    float pc[DOUT];
    #pragma unroll
    for (int c = 0; c < DOUT; c++) pc[c] = u * W2[j * DOUT + c];

    #pragma unroll
    for (int c = 0; c < DOUT; c++)
        #pragma unroll
        for (int o = 16; o > 0; o >>= 1)
            pc[c] += __shfl_xor_sync(0xffffffffu, pc[c], o);

    __shared__ float sp[8][DOUT];
    __shared__ float pooled[DOUT];
    __shared__ float mx_s, lse_s;

    const int w = j >> 5, lane = j & 31;
    if (lane == 0) {
        #pragma unroll
        for (int c = 0; c < DOUT; c++) sp[w][c] = pc[c];
    }
    __syncthreads();

    if (j < DOUT) {
        float v = b2[j];
        #pragma unroll
        for (int ww = 0; ww < 8; ww++) v += sp[ww][j];
        pooled[j] = v;
    }
    __syncthreads();

    if (j == 0) {
        float mx = pooled[0];
        #pragma unroll
        for (int c = 1; c < DOUT; c++) mx = fmaxf(mx, pooled[c]);
        float se = 0.f;
        #pragma unroll
        for (int c = 0; c < DOUT; c++) se += expf(pooled[c] - mx);
        mx_s = mx;
        lse_s = logf(se);
    }
    __syncthreads();

    if (j < DOUT) out[g * DOUT + j] = pooled[j] - mx_s - lse_s;
}

// ============================================================
extern "C" void kernel_launch(void* const* d_in, const int* in_sizes, int n_in,
                              void* d_out, int out_size) {
    const float* x  = (const float*)d_in[0];
    // d_in[1] = batch (int64) — sorted equal-sized graphs, not needed
    const float* W1 = (const float*)d_in[2];
    const float* b1 = (const float*)d_in[3];
    const float* W2 = (const float*)d_in[4];
    const float* b2 = (const float*)d_in[5];
    float* out = (float*)d_out;

    k_norms<<<GG, 512>>>(x);
    k_wvec<<<MT / 8, 256>>>(x);
    dim3 grid(DH / 128, MT / 128);
    k_main<<<grid, 256>>>(x, W1, b1);
    k_final<<<GG, 256>>>(W2, b2, out);
}

// round 4
// speedup vs baseline: 1.2875x; 1.2875x over previous
#include <cuda_runtime.h>
#include <cuda_bf16.h>
#include <math.h>
#include <stdint.h>

#define GG   64
#define NN   1024
#define DIN  128
#define DH   256
#define DOUT 10
#define MT   (GG * NN)          // 65536 nodes
#define NTILES (MT / 128)       // 512 row tiles
#define GRID_B 148

// ---- scratch (no allocations allowed) ----
__device__ float g_w[MT];               // per-node adjacency column-sum weight
__device__ float g_upart[NTILES * DH];  // per-tile partial of u = sum_m w_m h_m

// ================= helpers =================
__device__ __forceinline__ uint32_t s2u(const void* p) {
    uint32_t a;
    asm("{ .reg .u64 t; cvta.to.shared.u64 t, %1; cvt.u32.u64 %0, t; }" : "=r"(a) : "l"(p));
    return a;
}

// SMEM layout (bytes), K padded to 136 bf16 per row (272B, conflict-free ldmatrix)
#define KP        136
#define OFF_B1    0                       // 256 floats
#define OFF_WS    1024                    // 128 floats
#define OFF_RED   1536                    // 16 x 64 floats = 4096
#define OFF_AHI   5632                    // 128*136*2 = 34816
#define OFF_ALO   40448
#define OFF_BHI   75264                   // 256*136*2 = 69632
#define OFF_BLO   144896
#define SMEM_TOTAL 214528

// ============================================================
// Kernel 1 (fused): row inv-norms, s_g, then per-node weights
// ============================================================
__global__ __launch_bounds__(1024) void k_prep(const float* __restrict__ x) {
    const int g    = blockIdx.x;
    const int tid  = threadIdx.x;
    const int w    = tid >> 5;
    const int lane = tid & 31;

    __shared__ float spart[32][DIN];
    __shared__ float s_sh[DIN];
    __shared__ float inv_s[NN];
    __shared__ float sw_s[NN];

    float s0 = 0.f, s1 = 0.f, s2 = 0.f, s3 = 0.f;
    for (int n = w; n < NN; n += 32) {
        const int node = g * NN + n;
        const float4 v = *(const float4*)(x + (size_t)node * DIN + lane * 4);
        float sq = v.x * v.x + v.y * v.y + v.z * v.z + v.w * v.w;
        #pragma unroll
        for (int o = 16; o > 0; o >>= 1) sq += __shfl_xor_sync(0xffffffffu, sq, o);
        const float invn = rsqrtf(sq + 1e-24f);
        if (lane == 0) { inv_s[n] = invn; sw_s[n] = sq * invn * invn; }
        s0 += invn * v.x; s1 += invn * v.y; s2 += invn * v.z; s3 += invn * v.w;
    }
    spart[w][lane * 4 + 0] = s0;
    spart[w][lane * 4 + 1] = s1;
    spart[w][lane * 4 + 2] = s2;
    spart[w][lane * 4 + 3] = s3;
    __syncthreads();
    if (tid < DIN) {
        float s = 0.f;
        #pragma unroll
        for (int i = 0; i < 32; i++) s += spart[i][tid];
        s_sh[tid] = s;
    }
    __syncthreads();

    for (int n = w; n < NN; n += 32) {
        const int node = g * NN + n;
        const float4 v  = *(const float4*)(x + (size_t)node * DIN + lane * 4);
        const float4 sv = *(const float4*)(s_sh + lane * 4);
        float d = v.x * sv.x + v.y * sv.y + v.z * sv.z + v.w * sv.w;
        #pragma unroll
        for (int o = 16; o > 0; o >>= 1) d += __shfl_xor_sync(0xffffffffu, d, o);
        if (lane == 0) g_w[node] = inv_s[n] * d - sw_s[n];
    }
}

// ============================================================
// Kernel 2: persistent HMMA GEMM  h = relu(X@W1+b1) + epilogue
//   split-bf16 (hi,lo), 3 passes (hh, hi*lo_B, lo_A*hi) in fp32 acc
//   tile M=128, N=256, K=128; 16 warps, warp = 32x64
// ============================================================
__global__ __launch_bounds__(512, 1) void k_gemm(const float* __restrict__ x,
                                                 const float* __restrict__ W1,
                                                 const float* __restrict__ b1) {
    extern __shared__ __align__(16) char sm[];
    const uint32_t sb = s2u(sm);
    const int tid  = threadIdx.x;
    const int lane = tid & 31;
    const int wid  = tid >> 5;
    const int wm   = wid >> 2;   // 0..3 (M quadrant, 32 rows)
    const int wn   = wid & 3;    // 0..3 (N quadrant, 64 cols)

    float* b1s = (float*)(sm + OFF_B1);
    float* ws  = (float*)(sm + OFF_WS);
    float* red = (float*)(sm + OFF_RED);   // [16][64]

    // bias to smem
    if (tid < 256) b1s[tid] = b1[tid];

    // ---- convert W1 (K x N row-major) -> Bs[n][k] split bf16, once per CTA ----
    // 256 n-rows x 64 k-pairs = 16384 u32 entries -> 32 iters x 512 threads
    {
        uint32_t* bhi = (uint32_t*)(sm + OFF_BHI);
        uint32_t* blo = (uint32_t*)(sm + OFF_BLO);
        #pragma unroll 4
        for (int it = 0; it < 32; it++) {
            const int idx = it * 512 + tid;       // 0..16383
            const int n   = idx & 255;
            const int kp  = idx >> 8;             // 0..63 (k pair)
            const float v0 = W1[(2 * kp) * DH + n];
            const float v1 = W1[(2 * kp + 1) * DH + n];
            const __nv_bfloat16 h0 = __float2bfloat16(v0);
            const __nv_bfloat16 h1 = __float2bfloat16(v1);
            const __nv_bfloat16 l0 = __float2bfloat16(v0 - __bfloat162float(h0));
            const __nv_bfloat16 l1 = __float2bfloat16(v1 - __bfloat162float(h1));
            __nv_bfloat162 hp; hp.x = h0; hp.y = h1;
            __nv_bfloat162 lp; lp.x = l0; lp.y = l1;
            const int o = n * (KP / 2) + kp;      // u32 index: n*68 + kp
            bhi[o] = *(uint32_t*)&hp;
            blo[o] = *(uint32_t*)&lp;
        }
    }

    // ldmatrix lane offsets (element units)
    const int aoff = (wm * 32 + (lane & 7) + ((lane >> 3) & 1) * 8) * KP
                   + ((lane >> 4) & 1) * 8;
    const int lb   = lane & 15;
    const int boff = (wn * 64 + (lb & 7)) * KP + (lb >> 3) * 8;

    for (int t = blockIdx.x; t < NTILES; t += gridDim.x) {
        const int m0 = t * 128;

        // ---- convert A tile (128 x 128) split bf16 ----
        {
            uint32_t* ahi = (uint32_t*)(sm + OFF_AHI);
            uint32_t* alo = (uint32_t*)(sm + OFF_ALO);
            const int cp = tid & 63;              // col pair
            const int rq = tid >> 6;              // 0..7
            #pragma unroll 4
            for (int it = 0; it < 16; it++) {
                const int row = it * 8 + rq;
                const float2 v = *(const float2*)(x + (size_t)(m0 + row) * DIN + cp * 2);
                const __nv_bfloat16 h0 = __float2bfloat16(v.x);
                const __nv_bfloat16 h1 = __float2bfloat16(v.y);
                const __nv_bfloat16 l0 = __float2bfloat16(v.x - __bfloat162float(h0));
                const __nv_bfloat16 l1 = __float2bfloat16(v.y - __bfloat162float(h1));
                __nv_bfloat162 hp; hp.x = h0; hp.y = h1;
                __nv_bfloat162 lp; lp.x = l0; lp.y = l1;
                const int o = row * (KP / 2) + cp;
                ahi[o] = *(uint32_t*)&hp;
                alo[o] = *(uint32_t*)&lp;
            }
            if (tid < 128) ws[tid] = g_w[m0 + tid];
        }
        __syncthreads();

        // ---- 3-pass MMA into fp32 acc ----
        float acc[2][8][4];
        #pragma unroll
        for (int mi = 0; mi < 2; mi++)
            #pragma unroll
            for (int ni = 0; ni < 8; ni++)
                #pragma unroll
                for (int q = 0; q < 4; q++) acc[mi][ni][q] = 0.f;

        #pragma unroll
        for (int p = 0; p < 3; p++) {
            const uint32_t ab = sb + (p == 2 ? OFF_ALO : OFF_AHI);
            const uint32_t bb = sb + (p == 1 ? OFF_BLO : OFF_BHI);
            #pragma unroll
            for (int kc = 0; kc < 8; kc++) {
                uint32_t af[2][4];
                #pragma unroll
                for (int mi = 0; mi < 2; mi++) {
                    const uint32_t addr = ab + 2u * (aoff + mi * 16 * KP + kc * 16);
                    asm volatile(
                        "ldmatrix.sync.aligned.m8n8.x4.shared.b16 {%0,%1,%2,%3}, [%4];"
                        : "=r"(af[mi][0]), "=r"(af[mi][1]), "=r"(af[mi][2]), "=r"(af[mi][3])
                        : "r"(addr));
                }
                uint32_t bf[8][2];
                #pragma unroll
                for (int ni = 0; ni < 8; ni++) {
                    const uint32_t addr = bb + 2u * (boff + ni * 8 * KP + kc * 16);
                    asm volatile(
                        "ldmatrix.sync.aligned.m8n8.x2.shared.b16 {%0,%1}, [%2];"
                        : "=r"(bf[ni][0]), "=r"(bf[ni][1]) : "r"(addr));
                }
                #pragma unroll
                for (int mi = 0; mi < 2; mi++)
                    #pragma unroll
                    for (int ni = 0; ni < 8; ni++) {
                        asm volatile(
                            "mma.sync.aligned.m16n8k16.row.col.f32.bf16.bf16.f32 "
                            "{%0,%1,%2,%3}, {%4,%5,%6,%7}, {%8,%9}, {%0,%1,%2,%3};"
                            : "+f"(acc[mi][ni][0]), "+f"(acc[mi][ni][1]),
                              "+f"(acc[mi][ni][2]), "+f"(acc[mi][ni][3])
                            : "r"(af[mi][0]), "r"(af[mi][1]), "r"(af[mi][2]), "r"(af[mi][3]),
                              "r"(bf[ni][0]), "r"(bf[ni][1]));
                    }
            }
        }

        // ---- epilogue: +b1, relu, *w_m, column reduce ----
        float p0[8], p1[8];
        #pragma unroll
        for (int ni = 0; ni < 8; ni++) { p0[ni] = 0.f; p1[ni] = 0.f; }

        #pragma unroll
        for (int mi = 0; mi < 2; mi++) {
            const float w0 = ws[wm * 32 + mi * 16 + (lane >> 2)];
            const float w1 = ws[wm * 32 + mi * 16 + (lane >> 2) + 8];
            #pragma unroll
            for (int ni = 0; ni < 8; ni++) {
                const int cb = wn * 64 + ni * 8 + (lane & 3) * 2;
                const float bb0 = b1s[cb], bb1 = b1s[cb + 1];
                float h;
                h = acc[mi][ni][0] + bb0; h = h > 0.f ? h : 0.f; p0[ni] += w0 * h;
                h = acc[mi][ni][2] + bb0; h = h > 0.f ? h : 0.f; p0[ni] += w1 * h;
                h = acc[mi][ni][1] + bb1; h = h > 0.f ? h : 0.f; p1[ni] += w0 * h;
                h = acc[mi][ni][3] + bb1; h = h > 0.f ? h : 0.f; p1[ni] += w1 * h;
            }
        }
        #pragma unroll
        for (int ni = 0; ni < 8; ni++) {
            #pragma unroll
            for (int o = 4; o < 32; o <<= 1) {
                p0[ni] += __shfl_xor_sync(0xffffffffu, p0[ni], o);
                p1[ni] += __shfl_xor_sync(0xffffffffu, p1[ni], o);
            }
        }
        if (lane < 4) {
            #pragma unroll
            for (int ni = 0; ni < 8; ni++) {
                red[wid * 64 + ni * 8 + lane * 2]     = p0[ni];
                red[wid * 64 + ni * 8 + lane * 2 + 1] = p1[ni];
            }
        }
        __syncthreads();
        if (tid < 256) {
            const int wn_ = tid >> 6, cc = tid & 63;
            float s = red[(0 * 4 + wn_) * 64 + cc] + red[(1 * 4 + wn_) * 64 + cc]
                    + red[(2 * 4 + wn_) * 64 + cc] + red[(3 * 4 + wn_) * 64 + cc];
            g_upart[(size_t)t * DH + tid] = s;
        }
        __syncthreads();
    }
}

// ============================================================
// Kernel 3: reduce partials, (u/N) @ W2 + b2, log-softmax
// ============================================================
__global__ void k_final(const float* __restrict__ W2,
                        const float* __restrict__ b2,
                        float* __restrict__ out) {
    const int g = blockIdx.x;
    const int j = threadIdx.x;   // 0..255

    float u = 0.f;
    #pragma unroll
    for (int r = 0; r < 8; r++) u += g_upart[(size_t)(g * 8 + r) * DH + j];
    u *= (1.0f / NN);

    float pc[DOUT];
    #pragma unroll
    for (int c = 0; c < DOUT; c++) pc[c] = u * W2[j * DOUT + c];

    #pragma unroll
    for (int c = 0; c < DOUT; c++)
        #pragma unroll
        for (int o = 16; o > 0; o >>= 1)
            pc[c] += __shfl_xor_sync(0xffffffffu, pc[c], o);

    __shared__ float sp[8][DOUT];
    __shared__ float pooled[DOUT];
    __shared__ float mx_s, lse_s;

    const int w = j >> 5, lane = j & 31;
    if (lane == 0) {
        #pragma unroll
        for (int c = 0; c < DOUT; c++) sp[w][c] = pc[c];
    }
    __syncthreads();

    if (j < DOUT) {
        float v = b2[j];
        #pragma unroll
        for (int ww = 0; ww < 8; ww++) v += sp[ww][j];
        pooled[j] = v;
    }
    __syncthreads();

    if (j == 0) {
        float mx = pooled[0];
        #pragma unroll
        for (int c = 1; c < DOUT; c++) mx = fmaxf(mx, pooled[c]);
        float se = 0.f;
        #pragma unroll
        for (int c = 0; c < DOUT; c++) se += expf(pooled[c] - mx);
        mx_s = mx;
        lse_s = logf(se);
    }
    __syncthreads();

    if (j < DOUT) out[g * DOUT + j] = pooled[j] - mx_s - lse_s;
}

// ============================================================
extern "C" void kernel_launch(void* const* d_in, const int* in_sizes, int n_in,
                              void* d_out, int out_size) {
    const float* x  = (const float*)d_in[0];
    // d_in[1] = batch (int64) — sorted equal-sized graphs, not needed
    const float* W1 = (const float*)d_in[2];
    const float* b1 = (const float*)d_in[3];
    const float* W2 = (const float*)d_in[4];
    const float* b2 = (const float*)d_in[5];
    float* out = (float*)d_out;

    cudaFuncSetAttribute(k_gemm, cudaFuncAttributeMaxDynamicSharedMemorySize, SMEM_TOTAL);

    k_prep<<<GG, 1024>>>(x);
    k_gemm<<<GRID_B, 512, SMEM_TOTAL>>>(x, W1, b1);
    k_final<<<GG, 256>>>(W2, b2, out);
}

// round 5
// speedup vs baseline: 1.7438x; 1.3544x over previous
#include <cuda_runtime.h>
#include <cuda_bf16.h>
#include <math.h>
#include <stdint.h>

#define GG   64
#define NN   1024
#define DIN  128
#define DH   256
#define DOUT 10
#define MT   (GG * NN)          // 65536 nodes
#define NTILES (MT / 128)       // 512 row tiles
#define GRID_B 148

// ---- scratch (no allocations allowed) ----
__device__ float g_spart[512 * DIN];    // per-(graph,slice) partial of s_g
__device__ float g_upart[NTILES * DH];  // per-tile partial of u = sum_m w_m h_m

// ================= helpers =================
__device__ __forceinline__ uint32_t s2u(const void* p) {
    uint32_t a;
    asm("{ .reg .u64 t; cvta.to.shared.u64 t, %1; cvt.u32.u64 %0, t; }" : "=r"(a) : "l"(p));
    return a;
}

// SMEM layout (bytes), K padded to 136 bf16 per row (272B, conflict-free ldmatrix)
#define KP        136
#define OFF_B1    0                       // 256 floats
#define OFF_WS    1024                    // 128 floats
#define OFF_S     1536                    // 128 floats
#define OFF_RED   2048                    // 16 x 32 floats = 2048B
#define OFF_AHI   4096                    // 128*136*2 = 34816
#define OFF_ALO   38912
#define OFF_BHI   73728                   // 256*136*2 = 69632
#define OFF_BLO   143360
#define SMEM_TOTAL 212992

// ============================================================
// Kernel 1: partial s_g per (graph, slice of 128 nodes)
// grid = 512 CTAs (8 per graph) x 256 threads (8 warps x 16 rows)
// ============================================================
__global__ __launch_bounds__(256) void k_prep1(const float* __restrict__ x) {
    const int c    = blockIdx.x;
    const int g    = c >> 3;
    const int sl   = c & 7;
    const int tid  = threadIdx.x;
    const int w    = tid >> 5;
    const int lane = tid & 31;

    __shared__ float spart[8][DIN];

    float s0 = 0.f, s1 = 0.f, s2 = 0.f, s3 = 0.f;
    #pragma unroll
    for (int r = 0; r < 16; r++) {
        const int node = g * NN + sl * 128 + w * 16 + r;
        const float4 v = *(const float4*)(x + (size_t)node * DIN + lane * 4);
        float sq = v.x * v.x + v.y * v.y + v.z * v.z + v.w * v.w;
        #pragma unroll
        for (int o = 16; o > 0; o >>= 1) sq += __shfl_xor_sync(0xffffffffu, sq, o);
        const float invn = rsqrtf(sq + 1e-24f);
        s0 += invn * v.x; s1 += invn * v.y; s2 += invn * v.z; s3 += invn * v.w;
    }
    spart[w][lane * 4 + 0] = s0;
    spart[w][lane * 4 + 1] = s1;
    spart[w][lane * 4 + 2] = s2;
    spart[w][lane * 4 + 3] = s3;
    __syncthreads();
    if (tid < DIN) {
        float s = 0.f;
        #pragma unroll
        for (int i = 0; i < 8; i++) s += spart[i][tid];
        g_spart[c * DIN + tid] = s;
    }
}

// ============================================================
// Kernel 2: persistent HMMA GEMM  h = relu(X@W1+b1) + epilogue
//   split-bf16 (hi,lo), 3 passes (hh, hi*loB, loA*hi), fp32 acc
//   tile M=128, N=256, K=128; 16 warps as 2(wm) x 8(wn), warp=64x32
//   Also computes per-row weight w_m in the A-conversion pass.
// ============================================================
__global__ __launch_bounds__(512, 1) void k_gemm(const float* __restrict__ x,
                                                 const float* __restrict__ W1,
                                                 const float* __restrict__ b1) {
    extern __shared__ __align__(16) char sm[];
    const uint32_t sb = s2u(sm);
    const int tid  = threadIdx.x;
    const int lane = tid & 31;
    const int wid  = tid >> 5;
    const int wm   = wid >> 3;   // 0..1 (64-row half)
    const int wn   = wid & 7;    // 0..7 (32-col slice)

    float* b1s  = (float*)(sm + OFF_B1);
    float* ws   = (float*)(sm + OFF_WS);
    float* s_sh = (float*)(sm + OFF_S);
    float* red  = (float*)(sm + OFF_RED);   // [16][32]

    if (tid < 256) b1s[tid] = b1[tid];

    // ---- convert W1 (K x N row-major) -> Bs[n][k] split bf16, once per CTA ----
    {
        uint32_t* bhi = (uint32_t*)(sm + OFF_BHI);
        uint32_t* blo = (uint32_t*)(sm + OFF_BLO);
        #pragma unroll 4
        for (int it = 0; it < 32; it++) {
            const int idx = it * 512 + tid;       // 0..16383
            const int n   = idx & 255;
            const int kp  = idx >> 8;             // 0..63 (k pair)
            const float v0 = W1[(2 * kp) * DH + n];
            const float v1 = W1[(2 * kp + 1) * DH + n];
            const __nv_bfloat16 h0 = __float2bfloat16(v0);
            const __nv_bfloat16 h1 = __float2bfloat16(v1);
            const __nv_bfloat16 l0 = __float2bfloat16(v0 - __bfloat162float(h0));
            const __nv_bfloat16 l1 = __float2bfloat16(v1 - __bfloat162float(h1));
            __nv_bfloat162 hp; hp.x = h0; hp.y = h1;
            __nv_bfloat162 lp; lp.x = l0; lp.y = l1;
            const int o = n * (KP / 2) + kp;
            bhi[o] = *(uint32_t*)&hp;
            blo[o] = *(uint32_t*)&lp;
        }
    }

    // ldmatrix lane offsets (element units)
    const int arow_l = (lane & 7) + ((lane >> 3) & 1) * 8;
    const int acol_l = ((lane >> 4) & 1) * 8;
    const int aoff0  = (wm * 64 + arow_l) * KP + acol_l;
    const int brow_l = (lane & 7) + (lane >> 4) * 8;
    const int bcol_l = ((lane >> 3) & 1) * 8;
    const int boff0  = (wn * 32 + brow_l) * KP + bcol_l;

    for (int t = blockIdx.x; t < NTILES; t += gridDim.x) {
        const int m0  = t * 128;
        const int gph = t >> 3;

        // ---- s_g for this tile's graph (reduce 8 slice partials) ----
        if (tid < DIN) {
            float ssum = 0.f;
            #pragma unroll
            for (int sl = 0; sl < 8; sl++)
                ssum += g_spart[(gph * 8 + sl) * DIN + tid];
            s_sh[tid] = ssum;
        }
        __syncthreads();

        // ---- convert A tile (warp owns rows wid*8..+7) + compute w_m ----
        {
            uint32_t* ahi = (uint32_t*)(sm + OFF_AHI);
            uint32_t* alo = (uint32_t*)(sm + OFF_ALO);
            const float4 sv = *(const float4*)(s_sh + lane * 4);
            #pragma unroll
            for (int r = 0; r < 8; r++) {
                const int row = wid * 8 + r;
                const float4 v = *(const float4*)(x + (size_t)(m0 + row) * DIN + lane * 4);
                float sq = v.x * v.x + v.y * v.y + v.z * v.z + v.w * v.w;
                float dt = v.x * sv.x + v.y * sv.y + v.z * sv.z + v.w * sv.w;
                #pragma unroll
                for (int o = 16; o > 0; o >>= 1) {
                    sq += __shfl_xor_sync(0xffffffffu, sq, o);
                    dt += __shfl_xor_sync(0xffffffffu, dt, o);
                }
                const __nv_bfloat16 h0 = __float2bfloat16(v.x);
                const __nv_bfloat16 h1 = __float2bfloat16(v.y);
                const __nv_bfloat16 h2 = __float2bfloat16(v.z);
                const __nv_bfloat16 h3 = __float2bfloat16(v.w);
                const __nv_bfloat16 l0 = __float2bfloat16(v.x - __bfloat162float(h0));
                const __nv_bfloat16 l1 = __float2bfloat16(v.y - __bfloat162float(h1));
                const __nv_bfloat16 l2 = __float2bfloat16(v.z - __bfloat162float(h2));
                const __nv_bfloat16 l3 = __float2bfloat16(v.w - __bfloat162float(h3));
                __nv_bfloat162 hp0; hp0.x = h0; hp0.y = h1;
                __nv_bfloat162 hp1; hp1.x = h2; hp1.y = h3;
                __nv_bfloat162 lp0; lp0.x = l0; lp0.y = l1;
                __nv_bfloat162 lp1; lp1.x = l2; lp1.y = l3;
                const int o = row * (KP / 2) + lane * 2;
                ahi[o]     = *(uint32_t*)&hp0;
                ahi[o + 1] = *(uint32_t*)&hp1;
                alo[o]     = *(uint32_t*)&lp0;
                alo[o + 1] = *(uint32_t*)&lp1;
                if (lane == 0) {
                    const float invn = rsqrtf(sq + 1e-24f);
                    ws[row] = invn * dt - sq * invn * invn;
                }
            }
        }
        __syncthreads();

        // ---- 3-pass MMA into fp32 acc ----
        float acc[4][4][4];
        #pragma unroll
        for (int mi = 0; mi < 4; mi++)
            #pragma unroll
            for (int ni = 0; ni < 4; ni++)
                #pragma unroll
                for (int q = 0; q < 4; q++) acc[mi][ni][q] = 0.f;

        #pragma unroll
        for (int p = 0; p < 3; p++) {
            const uint32_t ab = sb + (p == 2 ? OFF_ALO : OFF_AHI);
            const uint32_t bb = sb + (p == 1 ? OFF_BLO : OFF_BHI);
            #pragma unroll
            for (int kc = 0; kc < 8; kc++) {
                uint32_t af[4][4];
                #pragma unroll
                for (int mi = 0; mi < 4; mi++) {
                    const uint32_t addr = ab + 2u * (aoff0 + mi * 16 * KP + kc * 16);
                    asm volatile(
                        "ldmatrix.sync.aligned.m8n8.x4.shared.b16 {%0,%1,%2,%3}, [%4];"
                        : "=r"(af[mi][0]), "=r"(af[mi][1]), "=r"(af[mi][2]), "=r"(af[mi][3])
                        : "r"(addr));
                }
                uint32_t bf[2][4];
                #pragma unroll
                for (int n2 = 0; n2 < 2; n2++) {
                    const uint32_t addr = bb + 2u * (boff0 + n2 * 16 * KP + kc * 16);
                    asm volatile(
                        "ldmatrix.sync.aligned.m8n8.x4.shared.b16 {%0,%1,%2,%3}, [%4];"
                        : "=r"(bf[n2][0]), "=r"(bf[n2][1]), "=r"(bf[n2][2]), "=r"(bf[n2][3])
                        : "r"(addr));
                }
                #pragma unroll
                for (int mi = 0; mi < 4; mi++)
                    #pragma unroll
                    for (int ni = 0; ni < 4; ni++) {
                        const int n2 = ni >> 1, sel = (ni & 1) * 2;
                        asm volatile(
                            "mma.sync.aligned.m16n8k16.row.col.f32.bf16.bf16.f32 "
                            "{%0,%1,%2,%3}, {%4,%5,%6,%7}, {%8,%9}, {%0,%1,%2,%3};"
                            : "+f"(acc[mi][ni][0]), "+f"(acc[mi][ni][1]),
                              "+f"(acc[mi][ni][2]), "+f"(acc[mi][ni][3])
                            : "r"(af[mi][0]), "r"(af[mi][1]), "r"(af[mi][2]), "r"(af[mi][3]),
                              "r"(bf[n2][sel]), "r"(bf[n2][sel + 1]));
                    }
            }
        }

        // ---- epilogue: +b1, relu, *w_m, column reduce ----
        float p0[4], p1[4];
        #pragma unroll
        for (int ni = 0; ni < 4; ni++) { p0[ni] = 0.f; p1[ni] = 0.f; }

        #pragma unroll
        for (int mi = 0; mi < 4; mi++) {
            const float w0 = ws[wm * 64 + mi * 16 + (lane >> 2)];
            const float w1 = ws[wm * 64 + mi * 16 + (lane >> 2) + 8];
            #pragma unroll
            for (int ni = 0; ni < 4; ni++) {
                const int cb = wn * 32 + ni * 8 + (lane & 3) * 2;
                const float bb0 = b1s[cb], bb1 = b1s[cb + 1];
                float h;
                h = acc[mi][ni][0] + bb0; h = h > 0.f ? h : 0.f; p0[ni] += w0 * h;
                h = acc[mi][ni][2] + bb0; h = h > 0.f ? h : 0.f; p0[ni] += w1 * h;
                h = acc[mi][ni][1] + bb1; h = h > 0.f ? h : 0.f; p1[ni] += w0 * h;
                h = acc[mi][ni][3] + bb1; h = h > 0.f ? h : 0.f; p1[ni] += w1 * h;
            }
        }
        #pragma unroll
        for (int ni = 0; ni < 4; ni++) {
            #pragma unroll
            for (int o = 4; o < 32; o <<= 1) {
                p0[ni] += __shfl_xor_sync(0xffffffffu, p0[ni], o);
                p1[ni] += __shfl_xor_sync(0xffffffffu, p1[ni], o);
            }
        }
        if (lane < 4) {
            #pragma unroll
            for (int ni = 0; ni < 4; ni++) {
                red[wid * 32 + ni * 8 + lane * 2]     = p0[ni];
                red[wid * 32 + ni * 8 + lane * 2 + 1] = p1[ni];
            }
        }
        __syncthreads();
        if (tid < 256) {
            const int wn_ = tid >> 5, cc = tid & 31;
            g_upart[(size_t)t * DH + tid] =
                red[wn_ * 32 + cc] + red[(8 + wn_) * 32 + cc];
        }
        __syncthreads();
    }
}

// ============================================================
// Kernel 3: reduce partials, (u/N) @ W2 + b2, log-softmax
// ============================================================
__global__ void k_final(const float* __restrict__ W2,
                        const float* __restrict__ b2,
                        float* __restrict__ out) {
    const int g = blockIdx.x;
    const int j = threadIdx.x;   // 0..255

    float u = 0.f;
    #pragma unroll
    for (int r = 0; r < 8; r++) u += g_upart[(size_t)(g * 8 + r) * DH + j];
    u *= (1.0f / NN);

    float pc[DOUT];
    #pragma unroll
    for (int c = 0; c < DOUT; c++) pc[c] = u * W2[j * DOUT + c];

    #pragma unroll
    for (int c = 0; c < DOUT; c++)
        #pragma unroll
        for (int o = 16; o > 0; o >>= 1)
            pc[c] += __shfl_xor_sync(0xffffffffu, pc[c], o);

    __shared__ float sp[8][DOUT];
    __shared__ float pooled[DOUT];
    __shared__ float mx_s, lse_s;

    const int w = j >> 5, lane = j & 31;
    if (lane == 0) {
        #pragma unroll
        for (int c = 0; c < DOUT; c++) sp[w][c] = pc[c];
    }
    __syncthreads();

    if (j < DOUT) {
        float v = b2[j];
        #pragma unroll
        for (int ww = 0; ww < 8; ww++) v += sp[ww][j];
        pooled[j] = v;
    }
    __syncthreads();

    if (j == 0) {
        float mx = pooled[0];
        #pragma unroll
        for (int c = 1; c < DOUT; c++) mx = fmaxf(mx, pooled[c]);
        float se = 0.f;
        #pragma unroll
        for (int c = 0; c < DOUT; c++) se += expf(pooled[c] - mx);
        mx_s = mx;
        lse_s = logf(se);
    }
    __syncthreads();

    if (j < DOUT) out[g * DOUT + j] = pooled[j] - mx_s - lse_s;
}

// ============================================================
extern "C" void kernel_launch(void* const* d_in, const int* in_sizes, int n_in,
                              void* d_out, int out_size) {
    const float* x  = (const float*)d_in[0];
    // d_in[1] = batch (int64) — sorted equal-sized graphs, not needed
    const float* W1 = (const float*)d_in[2];
    const float* b1 = (const float*)d_in[3];
    const float* W2 = (const float*)d_in[4];
    const float* b2 = (const float*)d_in[5];
    float* out = (float*)d_out;

    cudaFuncSetAttribute(k_gemm, cudaFuncAttributeMaxDynamicSharedMemorySize, SMEM_TOTAL);

    k_prep1<<<512, 256>>>(x);
    k_gemm<<<GRID_B, 512, SMEM_TOTAL>>>(x, W1, b1);
    k_final<<<GG, 256>>>(W2, b2, out);
}

// round 6
// speedup vs baseline: 2.3119x; 1.3258x over previous
#include <cuda_runtime.h>
#include <cuda_fp16.h>
#include <math.h>
#include <stdint.h>

#define GG   64
#define NN   1024
#define DIN  128
#define DH   256
#define DOUT 10
#define MT   (GG * NN)          // 65536 nodes
#define NTILES (MT / 128)       // 512 row tiles
#define GRID_B 148

// ---- scratch (no allocations allowed) ----
__device__ float g_spart[1024 * DIN];   // per-(graph,slice64) partial of s_g
__device__ float g_upart[NTILES * DH];  // per-tile partial of u = sum_m w_m h_m

// ================= helpers =================
__device__ __forceinline__ uint32_t s2u(const void* p) {
    uint32_t a;
    asm("{ .reg .u64 t; cvta.to.shared.u64 t, %1; cvt.u32.u64 %0, t; }" : "=r"(a) : "l"(p));
    return a;
}

// SMEM layout (bytes), K padded to 136 fp16 per row (272B, conflict-free ldmatrix)
#define KP        136
#define OFF_B1    0                       // 256 floats
#define OFF_WS    1024                    // 128 floats
#define OFF_S     1536                    // 128 floats
#define OFF_RED   2048                    // 16 x 32 floats
#define OFF_AHI   4096                    // 128*136*2 = 34816
#define OFF_BHI   38912                   // 256*136*2 = 69632
#define OFF_BLO   108544                  // 256*136*2 = 69632
#define SMEM_TOTAL 178176

// ============================================================
// Kernel 1: partial s_g per (graph, slice of 64 nodes)
// grid = 1024 CTAs (16 per graph) x 256 threads (8 warps x 8 rows)
// ============================================================
__global__ __launch_bounds__(256) void k_prep1(const float* __restrict__ x) {
    const int c    = blockIdx.x;
    const int g    = c >> 4;
    const int sl   = c & 15;
    const int tid  = threadIdx.x;
    const int w    = tid >> 5;
    const int lane = tid & 31;

    __shared__ float spart[8][DIN];

    float s0 = 0.f, s1 = 0.f, s2 = 0.f, s3 = 0.f;
    #pragma unroll
    for (int r = 0; r < 8; r++) {
        const int node = g * NN + sl * 64 + w * 8 + r;
        const float4 v = *(const float4*)(x + (size_t)node * DIN + lane * 4);
        float sq = v.x * v.x + v.y * v.y + v.z * v.z + v.w * v.w;
        #pragma unroll
        for (int o = 16; o > 0; o >>= 1) sq += __shfl_xor_sync(0xffffffffu, sq, o);
        const float invn = rsqrtf(sq + 1e-24f);
        s0 += invn * v.x; s1 += invn * v.y; s2 += invn * v.z; s3 += invn * v.w;
    }
    spart[w][lane * 4 + 0] = s0;
    spart[w][lane * 4 + 1] = s1;
    spart[w][lane * 4 + 2] = s2;
    spart[w][lane * 4 + 3] = s3;
    __syncthreads();
    if (tid < DIN) {
        float s = 0.f;
        #pragma unroll
        for (int i = 0; i < 8; i++) s += spart[i][tid];
        g_spart[c * DIN + tid] = s;
    }
}

// ============================================================
// Kernel 2: persistent HMMA GEMM  h = relu(X@W1+b1) + epilogue
//   fp16 2-pass: Ah*Bh + Ah*Bl (A = fp16(x); B = W1 split hi/lo)
//   tile M=128, N=256, K=128; 16 warps as 2(wm) x 8(wn), warp=64x32
//   Also computes per-row weight w_m during A conversion.
// ============================================================
__global__ __launch_bounds__(512, 1) void k_gemm(const float* __restrict__ x,
                                                 const float* __restrict__ W1,
                                                 const float* __restrict__ b1) {
    extern __shared__ __align__(16) char sm[];
    const uint32_t sb = s2u(sm);
    const int tid  = threadIdx.x;
    const int lane = tid & 31;
    const int wid  = tid >> 5;
    const int wm   = wid >> 3;   // 0..1 (64-row half)
    const int wn   = wid & 7;    // 0..7 (32-col slice)

    float* b1s  = (float*)(sm + OFF_B1);
    float* ws   = (float*)(sm + OFF_WS);
    float* s_sh = (float*)(sm + OFF_S);
    float* red  = (float*)(sm + OFF_RED);   // [16][32]

    if (tid < 256) b1s[tid] = b1[tid];

    // ---- convert W1 (K x N row-major) -> Bs[n][k] fp16 hi/lo, once per CTA ----
    {
        uint32_t* bhi = (uint32_t*)(sm + OFF_BHI);
        uint32_t* blo = (uint32_t*)(sm + OFF_BLO);
        #pragma unroll 4
        for (int it = 0; it < 32; it++) {
            const int idx = it * 512 + tid;       // 0..16383
            const int n   = idx & 255;
            const int kp  = idx >> 8;             // 0..63 (k pair)
            const float v0 = W1[(2 * kp) * DH + n];
            const float v1 = W1[(2 * kp + 1) * DH + n];
            const __half h0 = __float2half_rn(v0);
            const __half h1 = __float2half_rn(v1);
            const __half l0 = __float2half_rn(v0 - __half2float(h0));
            const __half l1 = __float2half_rn(v1 - __half2float(h1));
            __half2 hp; hp.x = h0; hp.y = h1;
            __half2 lp; lp.x = l0; lp.y = l1;
            const int o = n * (KP / 2) + kp;
            bhi[o] = *(uint32_t*)&hp;
            blo[o] = *(uint32_t*)&lp;
        }
    }

    // ldmatrix lane offsets (element units)
    const int arow_l = (lane & 7) + ((lane >> 3) & 1) * 8;
    const int acol_l = ((lane >> 4) & 1) * 8;
    const int aoff0  = (wm * 64 + arow_l) * KP + acol_l;
    const int brow_l = (lane & 7) + (lane >> 4) * 8;
    const int bcol_l = ((lane >> 3) & 1) * 8;
    const int boff0  = (wn * 32 + brow_l) * KP + bcol_l;

    for (int t = blockIdx.x; t < NTILES; t += gridDim.x) {
        const int m0  = t * 128;
        const int gph = t >> 3;

        // ---- s_g for this tile's graph (reduce 16 slice partials) ----
        if (tid < DIN) {
            float ssum = 0.f;
            #pragma unroll
            for (int sl = 0; sl < 16; sl++)
                ssum += g_spart[(gph * 16 + sl) * DIN + tid];
            s_sh[tid] = ssum;
        }
        __syncthreads();

        // ---- convert A tile (warp owns rows wid*8..+7) + compute w_m ----
        {
            uint32_t* ahi = (uint32_t*)(sm + OFF_AHI);
            const float4 sv = *(const float4*)(s_sh + lane * 4);
            #pragma unroll
            for (int r = 0; r < 8; r++) {
                const int row = wid * 8 + r;
                const float4 v = *(const float4*)(x + (size_t)(m0 + row) * DIN + lane * 4);
                float sq = v.x * v.x + v.y * v.y + v.z * v.z + v.w * v.w;
                float dt = v.x * sv.x + v.y * sv.y + v.z * sv.z + v.w * sv.w;
                #pragma unroll
                for (int o = 16; o > 0; o >>= 1) {
                    sq += __shfl_xor_sync(0xffffffffu, sq, o);
                    dt += __shfl_xor_sync(0xffffffffu, dt, o);
                }
                __half2 hp0 = __floats2half2_rn(v.x, v.y);
                __half2 hp1 = __floats2half2_rn(v.z, v.w);
                const int o = row * (KP / 2) + lane * 2;
                ahi[o]     = *(uint32_t*)&hp0;
                ahi[o + 1] = *(uint32_t*)&hp1;
                if (lane == 0) {
                    const float invn = rsqrtf(sq + 1e-24f);
                    ws[row] = invn * dt - sq * invn * invn;
                }
            }
        }
        __syncthreads();

        // ---- 2-pass MMA into fp32 acc ----
        float acc[4][4][4];
        #pragma unroll
        for (int mi = 0; mi < 4; mi++)
            #pragma unroll
            for (int ni = 0; ni < 4; ni++)
                #pragma unroll
                for (int q = 0; q < 4; q++) acc[mi][ni][q] = 0.f;

        #pragma unroll
        for (int p = 0; p < 2; p++) {
            const uint32_t ab = sb + OFF_AHI;
            const uint32_t bb = sb + (p == 1 ? OFF_BLO : OFF_BHI);
            #pragma unroll
            for (int kc = 0; kc < 8; kc++) {
                uint32_t af[4][4];
                #pragma unroll
                for (int mi = 0; mi < 4; mi++) {
                    const uint32_t addr = ab + 2u * (aoff0 + mi * 16 * KP + kc * 16);
                    asm volatile(
                        "ldmatrix.sync.aligned.m8n8.x4.shared.b16 {%0,%1,%2,%3}, [%4];"
                        : "=r"(af[mi][0]), "=r"(af[mi][1]), "=r"(af[mi][2]), "=r"(af[mi][3])
                        : "r"(addr));
                }
                uint32_t bf[2][4];
                #pragma unroll
                for (int n2 = 0; n2 < 2; n2++) {
                    const uint32_t addr = bb + 2u * (boff0 + n2 * 16 * KP + kc * 16);
                    asm volatile(
                        "ldmatrix.sync.aligned.m8n8.x4.shared.b16 {%0,%1,%2,%3}, [%4];"
                        : "=r"(bf[n2][0]), "=r"(bf[n2][1]), "=r"(bf[n2][2]), "=r"(bf[n2][3])
                        : "r"(addr));
                }
                #pragma unroll
                for (int mi = 0; mi < 4; mi++)
                    #pragma unroll
                    for (int ni = 0; ni < 4; ni++) {
                        const int n2 = ni >> 1, sel = (ni & 1) * 2;
                        asm volatile(
                            "mma.sync.aligned.m16n8k16.row.col.f32.f16.f16.f32 "
                            "{%0,%1,%2,%3}, {%4,%5,%6,%7}, {%8,%9}, {%0,%1,%2,%3};"
                            : "+f"(acc[mi][ni][0]), "+f"(acc[mi][ni][1]),
                              "+f"(acc[mi][ni][2]), "+f"(acc[mi][ni][3])
                            : "r"(af[mi][0]), "r"(af[mi][1]), "r"(af[mi][2]), "r"(af[mi][3]),
                              "r"(bf[n2][sel]), "r"(bf[n2][sel + 1]));
                    }
            }
        }

        // ---- epilogue: +b1, relu, *w_m, column reduce ----
        float p0[4], p1[4];
        #pragma unroll
        for (int ni = 0; ni < 4; ni++) { p0[ni] = 0.f; p1[ni] = 0.f; }

        #pragma unroll
        for (int mi = 0; mi < 4; mi++) {
            const float w0 = ws[wm * 64 + mi * 16 + (lane >> 2)];
            const float w1 = ws[wm * 64 + mi * 16 + (lane >> 2) + 8];
            #pragma unroll
            for (int ni = 0; ni < 4; ni++) {
                const int cb = wn * 32 + ni * 8 + (lane & 3) * 2;
                const float bb0 = b1s[cb], bb1 = b1s[cb + 1];
                float h;
                h = acc[mi][ni][0] + bb0; h = h > 0.f ? h : 0.f; p0[ni] += w0 * h;
                h = acc[mi][ni][2] + bb0; h = h > 0.f ? h : 0.f; p0[ni] += w1 * h;
                h = acc[mi][ni][1] + bb1; h = h > 0.f ? h : 0.f; p1[ni] += w0 * h;
                h = acc[mi][ni][3] + bb1; h = h > 0.f ? h : 0.f; p1[ni] += w1 * h;
            }
        }
        #pragma unroll
        for (int ni = 0; ni < 4; ni++) {
            #pragma unroll
            for (int o = 4; o < 32; o <<= 1) {
                p0[ni] += __shfl_xor_sync(0xffffffffu, p0[ni], o);
                p1[ni] += __shfl_xor_sync(0xffffffffu, p1[ni], o);
            }
        }
        if (lane < 4) {
            #pragma unroll
            for (int ni = 0; ni < 4; ni++) {
                red[wid * 32 + ni * 8 + lane * 2]     = p0[ni];
                red[wid * 32 + ni * 8 + lane * 2 + 1] = p1[ni];
            }
        }
        __syncthreads();
        if (tid < 256) {
            const int wn_ = tid >> 5, cc = tid & 31;
            g_upart[(size_t)t * DH + tid] =
                red[wn_ * 32 + cc] + red[(8 + wn_) * 32 + cc];
        }
        __syncthreads();
    }
}

// ============================================================
// Kernel 3: reduce partials, (u/N) @ W2 + b2, log-softmax
// ============================================================
__global__ void k_final(const float* __restrict__ W2,
                        const float* __restrict__ b2,
                        float* __restrict__ out) {
    const int g = blockIdx.x;
    const int j = threadIdx.x;   // 0..255

    float u = 0.f;
    #pragma unroll
    for (int r = 0; r < 8; r++) u += g_upart[(size_t)(g * 8 + r) * DH + j];
    u *= (1.0f / NN);

    float pc[DOUT];
    #pragma unroll
    for (int c = 0; c < DOUT; c++) pc[c] = u * W2[j * DOUT + c];

    #pragma unroll
    for (int c = 0; c < DOUT; c++)
        #pragma unroll
        for (int o = 16; o > 0; o >>= 1)
            pc[c] += __shfl_xor_sync(0xffffffffu, pc[c], o);

    __shared__ float sp[8][DOUT];
    __shared__ float pooled[DOUT];
    __shared__ float mx_s, lse_s;

    const int w = j >> 5, lane = j & 31;
    if (lane == 0) {
        #pragma unroll
        for (int c = 0; c < DOUT; c++) sp[w][c] = pc[c];
    }
    __syncthreads();

    if (j < DOUT) {
        float v = b2[j];
        #pragma unroll
        for (int ww = 0; ww < 8; ww++) v += sp[ww][j];
        pooled[j] = v;
    }
    __syncthreads();

    if (j == 0) {
        float mx = pooled[0];
        #pragma unroll
        for (int c = 1; c < DOUT; c++) mx = fmaxf(mx, pooled[c]);
        float se = 0.f;
        #pragma unroll
        for (int c = 0; c < DOUT; c++) se += expf(pooled[c] - mx);
        mx_s = mx;
        lse_s = logf(se);
    }
    __syncthreads();

    if (j < DOUT) out[g * DOUT + j] = pooled[j] - mx_s - lse_s;
}

// ============================================================
extern "C" void kernel_launch(void* const* d_in, const int* in_sizes, int n_in,
                              void* d_out, int out_size) {
    const float* x  = (const float*)d_in[0];
    // d_in[1] = batch (int64) — sorted equal-sized graphs, not needed
    const float* W1 = (const float*)d_in[2];
    const float* b1 = (const float*)d_in[3];
    const float* W2 = (const float*)d_in[4];
    const float* b2 = (const float*)d_in[5];
    float* out = (float*)d_out;

    cudaFuncSetAttribute(k_gemm, cudaFuncAttributeMaxDynamicSharedMemorySize, SMEM_TOTAL);

    k_prep1<<<1024, 256>>>(x);
    k_gemm<<<GRID_B, 512, SMEM_TOTAL>>>(x, W1, b1);
    k_final<<<GG, 256>>>(W2, b2, out);
}

// round 7
// speedup vs baseline: 3.5994x; 1.5569x over previous
#include <cuda_runtime.h>
#include <cuda_fp16.h>
#include <math.h>
#include <stdint.h>

#define GG   64
#define NN   1024
#define DIN  128
#define DH   256
#define DOUT 10
#define MT   (GG * NN)          // 65536 nodes
#define NTILES (MT / 128)       // 512 row tiles
#define GRID_B 148

// ---- scratch (no allocations allowed) ----
__device__ float g_spart[1024 * DIN];   // per-(graph,slice64) partial of s_g
__device__ float g_upart[NTILES * DH];  // per-tile partial of u = sum_m w_m h_m
__device__ int   g_cnt[GG];             // per-graph tile arrival counter

// ================= helpers =================
__device__ __forceinline__ uint32_t s2u(const void* p) {
    uint32_t a;
    asm("{ .reg .u64 t; cvta.to.shared.u64 t, %1; cvt.u32.u64 %0, t; }" : "=r"(a) : "l"(p));
    return a;
}

// SMEM layout (bytes), K padded to 136 fp16 per row (272B, conflict-free ldmatrix)
#define KP        136
#define OFF_B1    0                       // 256 floats
#define OFF_WS    1024                    // 128 floats
#define OFF_S     1536                    // 128 floats
#define OFF_RED   2048                    // 16 x 32 floats
#define OFF_FIN   4096                    // final-reduce scratch (512B)
#define OFF_AHI   4608                    // 128*136*2 = 34816
#define OFF_BHI   39424                   // 256*136*2 = 69632
#define SMEM_TOTAL 109056

// ============================================================
// Kernel 1: partial s_g per (graph, slice of 64 nodes)
// grid = 1024 CTAs x 256 threads; also resets g_cnt.
// ============================================================
__global__ __launch_bounds__(256) void k_prep1(const float* __restrict__ x) {
    const int c    = blockIdx.x;
    const int g    = c >> 4;
    const int sl   = c & 15;
    const int tid  = threadIdx.x;
    const int w    = tid >> 5;
    const int lane = tid & 31;

    if (c < GG && tid == 0) g_cnt[c] = 0;

    __shared__ float spart[8][DIN];

    float s0 = 0.f, s1 = 0.f, s2 = 0.f, s3 = 0.f;
    const int base = g * NN + sl * 64 + w * 8;
    #pragma unroll
    for (int r = 0; r < 8; r += 2) {
        const float4 va = *(const float4*)(x + (size_t)(base + r)     * DIN + lane * 4);
        const float4 vb = *(const float4*)(x + (size_t)(base + r + 1) * DIN + lane * 4);
        float sqa = va.x * va.x + va.y * va.y + va.z * va.z + va.w * va.w;
        float sqb = vb.x * vb.x + vb.y * vb.y + vb.z * vb.z + vb.w * vb.w;
        #pragma unroll
        for (int o = 16; o > 0; o >>= 1) {
            sqa += __shfl_xor_sync(0xffffffffu, sqa, o);
            sqb += __shfl_xor_sync(0xffffffffu, sqb, o);
        }
        const float ia = rsqrtf(sqa + 1e-24f);
        const float ib = rsqrtf(sqb + 1e-24f);
        s0 += ia * va.x + ib * vb.x;
        s1 += ia * va.y + ib * vb.y;
        s2 += ia * va.z + ib * vb.z;
        s3 += ia * va.w + ib * vb.w;
    }
    spart[w][lane * 4 + 0] = s0;
    spart[w][lane * 4 + 1] = s1;
    spart[w][lane * 4 + 2] = s2;
    spart[w][lane * 4 + 3] = s3;
    __syncthreads();
    if (tid < DIN) {
        float s = 0.f;
        #pragma unroll
        for (int i = 0; i < 8; i++) s += spart[i][tid];
        g_spart[c * DIN + tid] = s;
    }
}

// ============================================================
// Kernel 2: persistent HMMA GEMM  h = relu(X@W1+b1) + epilogue
//   single-pass fp16 (A=fp16(x), B=fp16(W1)), fp32 accumulate.
//   tile M=128, N=256, K=128; 16 warps as 2(wm) x 8(wn), warp=64x32.
//   Computes w_m during A conversion; last CTA per graph runs the
//   final (u/N)@W2+b2 + log-softmax inline.
// ============================================================
__global__ __launch_bounds__(512, 1) void k_gemm(const float* __restrict__ x,
                                                 const float* __restrict__ W1,
                                                 const float* __restrict__ b1,
                                                 const float* __restrict__ W2,
                                                 const float* __restrict__ b2,
                                                 float* __restrict__ out) {
    extern __shared__ __align__(16) char sm[];
    const uint32_t sb = s2u(sm);
    const int tid  = threadIdx.x;
    const int lane = tid & 31;
    const int wid  = tid >> 5;
    const int wm   = wid >> 3;   // 0..1 (64-row half)
    const int wn   = wid & 7;    // 0..7 (32-col slice)

    float* b1s  = (float*)(sm + OFF_B1);
    float* ws   = (float*)(sm + OFF_WS);
    float* s_sh = (float*)(sm + OFF_S);
    float* red  = (float*)(sm + OFF_RED);   // [16][32]
    float* fin  = (float*)(sm + OFF_FIN);   // final scratch
    int*   flag = (int*)(sm + OFF_FIN + 508);

    if (tid < 256) b1s[tid] = b1[tid];

    // ---- convert W1 (K x N row-major) -> Bs[n][k] fp16, once per CTA ----
    {
        uint32_t* bhi = (uint32_t*)(sm + OFF_BHI);
        #pragma unroll 4
        for (int it = 0; it < 32; it++) {
            const int idx = it * 512 + tid;       // 0..16383
            const int n   = idx & 255;
            const int kp  = idx >> 8;             // 0..63 (k pair)
            const float v0 = W1[(2 * kp) * DH + n];
            const float v1 = W1[(2 * kp + 1) * DH + n];
            __half2 hp = __floats2half2_rn(v0, v1);
            bhi[n * (KP / 2) + kp] = *(uint32_t*)&hp;
        }
    }

    // ldmatrix lane offsets (element units)
    const int arow_l = (lane & 7) + ((lane >> 3) & 1) * 8;
    const int acol_l = ((lane >> 4) & 1) * 8;
    const int aoff0  = (wm * 64 + arow_l) * KP + acol_l;
    const int brow_l = (lane & 7) + (lane >> 4) * 8;
    const int bcol_l = ((lane >> 3) & 1) * 8;
    const int boff0  = (wn * 32 + brow_l) * KP + bcol_l;

    for (int t = blockIdx.x; t < NTILES; t += gridDim.x) {
        const int m0  = t * 128;
        const int gph = t >> 3;

        // ---- s_g for this tile's graph (reduce 16 slice partials) ----
        if (tid < DIN) {
            float ssum = 0.f;
            #pragma unroll
            for (int sl = 0; sl < 16; sl++)
                ssum += g_spart[(gph * 16 + sl) * DIN + tid];
            s_sh[tid] = ssum;
        }
        __syncthreads();

        // ---- convert A tile (warp owns rows wid*8..+7) + compute w_m ----
        {
            uint32_t* ahi = (uint32_t*)(sm + OFF_AHI);
            const float4 sv = *(const float4*)(s_sh + lane * 4);
            #pragma unroll
            for (int r = 0; r < 8; r++) {
                const int row = wid * 8 + r;
                const float4 v = *(const float4*)(x + (size_t)(m0 + row) * DIN + lane * 4);
                float sq = v.x * v.x + v.y * v.y + v.z * v.z + v.w * v.w;
                float dt = v.x * sv.x + v.y * sv.y + v.z * sv.z + v.w * sv.w;
                #pragma unroll
                for (int o = 16; o > 0; o >>= 1) {
                    sq += __shfl_xor_sync(0xffffffffu, sq, o);
                    dt += __shfl_xor_sync(0xffffffffu, dt, o);
                }
                __half2 hp0 = __floats2half2_rn(v.x, v.y);
                __half2 hp1 = __floats2half2_rn(v.z, v.w);
                const int o = row * (KP / 2) + lane * 2;
                ahi[o]     = *(uint32_t*)&hp0;
                ahi[o + 1] = *(uint32_t*)&hp1;
                if (lane == 0) {
                    const float invn = rsqrtf(sq + 1e-24f);
                    ws[row] = invn * dt - sq * invn * invn;
                }
            }
        }
        __syncthreads();

        // ---- single-pass MMA into fp32 acc ----
        float acc[4][4][4];
        #pragma unroll
        for (int mi = 0; mi < 4; mi++)
            #pragma unroll
            for (int ni = 0; ni < 4; ni++)
                #pragma unroll
                for (int q = 0; q < 4; q++) acc[mi][ni][q] = 0.f;

        {
            const uint32_t ab = sb + OFF_AHI;
            const uint32_t bb = sb + OFF_BHI;
            #pragma unroll
            for (int kc = 0; kc < 8; kc++) {
                uint32_t af[4][4];
                #pragma unroll
                for (int mi = 0; mi < 4; mi++) {
                    const uint32_t addr = ab + 2u * (aoff0 + mi * 16 * KP + kc * 16);
                    asm volatile(
                        "ldmatrix.sync.aligned.m8n8.x4.shared.b16 {%0,%1,%2,%3}, [%4];"
                        : "=r"(af[mi][0]), "=r"(af[mi][1]), "=r"(af[mi][2]), "=r"(af[mi][3])
                        : "r"(addr));
                }
                uint32_t bf[2][4];
                #pragma unroll
                for (int n2 = 0; n2 < 2; n2++) {
                    const uint32_t addr = bb + 2u * (boff0 + n2 * 16 * KP + kc * 16);
                    asm volatile(
                        "ldmatrix.sync.aligned.m8n8.x4.shared.b16 {%0,%1,%2,%3}, [%4];"
                        : "=r"(bf[n2][0]), "=r"(bf[n2][1]), "=r"(bf[n2][2]), "=r"(bf[n2][3])
                        : "r"(addr));
                }
                #pragma unroll
                for (int mi = 0; mi < 4; mi++)
                    #pragma unroll
                    for (int ni = 0; ni < 4; ni++) {
                        const int n2 = ni >> 1, sel = (ni & 1) * 2;
                        asm volatile(
                            "mma.sync.aligned.m16n8k16.row.col.f32.f16.f16.f32 "
                            "{%0,%1,%2,%3}, {%4,%5,%6,%7}, {%8,%9}, {%0,%1,%2,%3};"
                            : "+f"(acc[mi][ni][0]), "+f"(acc[mi][ni][1]),
                              "+f"(acc[mi][ni][2]), "+f"(acc[mi][ni][3])
                            : "r"(af[mi][0]), "r"(af[mi][1]), "r"(af[mi][2]), "r"(af[mi][3]),
                              "r"(bf[n2][sel]), "r"(bf[n2][sel + 1]));
                    }
            }
        }

        // ---- epilogue: +b1, relu, *w_m, column reduce ----
        float p0[4], p1[4];
        #pragma unroll
        for (int ni = 0; ni < 4; ni++) { p0[ni] = 0.f; p1[ni] = 0.f; }

        #pragma unroll
        for (int mi = 0; mi < 4; mi++) {
            const float w0 = ws[wm * 64 + mi * 16 + (lane >> 2)];
            const float w1 = ws[wm * 64 + mi * 16 + (lane >> 2) + 8];
            #pragma unroll
            for (int ni = 0; ni < 4; ni++) {
                const int cb = wn * 32 + ni * 8 + (lane & 3) * 2;
                const float bb0 = b1s[cb], bb1 = b1s[cb + 1];
                float h;
                h = acc[mi][ni][0] + bb0; h = h > 0.f ? h : 0.f; p0[ni] += w0 * h;
                h = acc[mi][ni][2] + bb0; h = h > 0.f ? h : 0.f; p0[ni] += w1 * h;
                h = acc[mi][ni][1] + bb1; h = h > 0.f ? h : 0.f; p1[ni] += w0 * h;
                h = acc[mi][ni][3] + bb1; h = h > 0.f ? h : 0.f; p1[ni] += w1 * h;
            }
        }
        #pragma unroll
        for (int ni = 0; ni < 4; ni++) {
            #pragma unroll
            for (int o = 4; o < 32; o <<= 1) {
                p0[ni] += __shfl_xor_sync(0xffffffffu, p0[ni], o);
                p1[ni] += __shfl_xor_sync(0xffffffffu, p1[ni], o);
            }
        }
        if (lane < 4) {
            #pragma unroll
            for (int ni = 0; ni < 4; ni++) {
                red[wid * 32 + ni * 8 + lane * 2]     = p0[ni];
                red[wid * 32 + ni * 8 + lane * 2 + 1] = p1[ni];
            }
        }
        __syncthreads();
        if (tid < 256) {
            const int wn_ = tid >> 5, cc = tid & 31;
            g_upart[(size_t)t * DH + tid] =
                red[wn_ * 32 + cc] + red[(8 + wn_) * 32 + cc];
        }

        // ---- release our partial; last CTA of this graph runs the final ----
        __threadfence();
        __syncthreads();
        if (tid == 0) {
            const int old = atomicAdd(&g_cnt[gph], 1);
            *flag = (old == 7) ? 1 : 0;
        }
        __syncthreads();

        if (*flag) {
            // acquire
            if (tid == 0) __threadfence();
            __syncthreads();

            float pc[DOUT];
            const bool act = (tid < 256);
            if (act) {
                float u = 0.f;
                #pragma unroll
                for (int r = 0; r < 8; r++)
                    u += __ldcg(&g_upart[(size_t)(gph * 8 + r) * DH + tid]);
                u *= (1.0f / NN);
                #pragma unroll
                for (int c = 0; c < DOUT; c++) pc[c] = u * W2[tid * DOUT + c];
                #pragma unroll
                for (int c = 0; c < DOUT; c++)
                    #pragma unroll
                    for (int o = 16; o > 0; o >>= 1)
                        pc[c] += __shfl_xor_sync(0xffffffffu, pc[c], o);
                if (lane == 0) {
                    #pragma unroll
                    for (int c = 0; c < DOUT; c++) fin[wid * DOUT + c] = pc[c];
                }
            }
            __syncthreads();
            if (tid < DOUT) {
                float v = b2[tid];
                #pragma unroll
                for (int ww = 0; ww < 8; ww++) v += fin[ww * DOUT + tid];
                fin[96 + tid] = v;     // pooled
            }
            __syncthreads();
            if (tid == 0) {
                float mx = fin[96];
                #pragma unroll
                for (int c = 1; c < DOUT; c++) mx = fmaxf(mx, fin[96 + c]);
                float se = 0.f;
                #pragma unroll
                for (int c = 0; c < DOUT; c++) se += expf(fin[96 + c] - mx);
                fin[110] = mx;
                fin[111] = logf(se);
            }
            __syncthreads();
            if (tid < DOUT)
                out[gph * DOUT + tid] = fin[96 + tid] - fin[110] - fin[111];
        }
        __syncthreads();
    }
}

// ============================================================
extern "C" void kernel_launch(void* const* d_in, const int* in_sizes, int n_in,
                              void* d_out, int out_size) {
    const float* x  = (const float*)d_in[0];
    // d_in[1] = batch (int64) — sorted equal-sized graphs, not needed
    const float* W1 = (const float*)d_in[2];
    const float* b1 = (const float*)d_in[3];
    const float* W2 = (const float*)d_in[4];
    const float* b2 = (const float*)d_in[5];
    float* out = (float*)d_out;

    cudaFuncSetAttribute(k_gemm, cudaFuncAttributeMaxDynamicSharedMemorySize, SMEM_TOTAL);

    k_prep1<<<1024, 256>>>(x);
    k_gemm<<<GRID_B, 512, SMEM_TOTAL>>>(x, W1, b1, W2, b2, out);
}